// round 12
// baseline (speedup 1.0000x reference)
#include <cuda_runtime.h>
#include <math.h>
#include <stdint.h>

// ln(2)^2 — final scale converting lg2-unit squared-loss into natural-log units
#define LN2SQ 0.4804530139182014

// statically-zeroed accumulators; kernel self-resets them after each use,
// so the zero-invariant holds across the correctness run and every graph replay.
__device__ double g_accum = 0.0;
__device__ unsigned int g_count = 0u;

// ---- flag-independent fast approx intrinsics (MUFU paths) ----
__device__ __forceinline__ float f_rcp(float x)   { float y; asm("rcp.approx.f32 %0, %1;"   : "=f"(y) : "f"(x)); return y; }
__device__ __forceinline__ float f_rsqrt(float x) { float y; asm("rsqrt.approx.f32 %0, %1;" : "=f"(y) : "f"(x)); return y; }
__device__ __forceinline__ float f_sqrt(float x)  { float y; asm("sqrt.approx.f32 %0, %1;"  : "=f"(y) : "f"(x)); return y; }
__device__ __forceinline__ float f_lg2(float x)   { float y; asm("lg2.approx.f32 %0, %1;"   : "=f"(y) : "f"(x)); return y; }
__device__ __forceinline__ float f_cos(float x)   { float y; asm("cos.approx.f32 %0, %1;"   : "=f"(y) : "f"(x)); return y; }

// Abramowitz & Stegun 4.4.46: |err| <= 2e-8 rad on [0,1], extended to [-1,1]
__device__ __forceinline__ float fast_acos(float r) {
    float a = fabsf(r);
    float p = -0.0012624911f;
    p = fmaf(p, a,  0.0066700901f);
    p = fmaf(p, a, -0.0170881256f);
    p = fmaf(p, a,  0.0308918810f);
    p = fmaf(p, a, -0.0501743046f);
    p = fmaf(p, a,  0.0889789874f);
    p = fmaf(p, a, -0.2145988016f);
    p = fmaf(p, a,  1.5707963050f);
    float t = f_sqrt(fmaxf(1.0f - a, 0.0f)) * p;
    return (r < 0.0f) ? (3.14159265359f - t) : t;
}

struct Sym3 { float m00, m10, m11, m20, m21, m22; };

// logm (in lg2 units) of a 3x3 SPD matrix — identical math to the proven
// R9/R11 path (trig eigenvalues, single-rcp clamped Newton divided diffs).
__device__ __forceinline__ void log_spd3(const float* __restrict__ g, Sym3& L) {
    float a00 = g[0];
    float a10 = g[3];
    float a11 = g[4];
    float a20 = g[6];
    float a21 = g[7];
    float a22 = g[8];

    // ---- eigenvalues: trigonometric method (Smith) ----
    float q   = (a00 + a11 + a22) * (1.0f / 3.0f);
    float b00 = a00 - q, b11 = a11 - q, b22 = a22 - q;
    float p1  = a10 * a10 + a20 * a20 + a21 * a21;
    float p2  = b00 * b00 + b11 * b11 + b22 * b22 + 2.0f * p1;
    float x   = p2 * (1.0f / 6.0f);
    float rs  = f_rsqrt(fmaxf(x, 1e-30f));   // 1/sqrt(x)
    float p   = x * rs;                      // sqrt(x)

    float detB = b00 * (b11 * b22 - a21 * a21)
               - a10 * (a10 * b22 - a21 * a20)
               + a20 * (a10 * a21 - b11 * a20);
    float r = detB * (rs * rs) * (0.5f * rs);
    r = fmaxf(-1.0f, fminf(1.0f, r));        // also squashes NaN -> 1

    float phi = fast_acos(r) * (1.0f / 3.0f);
    float tp  = 2.0f * p;
    float w0 = fmaf(tp, f_cos(phi), q);                          // largest
    float w2 = fmaf(tp, f_cos(phi + 2.0943951023931953f), q);    // smallest
    float w1 = fmaf(3.0f, q, -w0) - w2;                          // middle

    // logs in base-2; final loss rescaled once by ln(2)^2
    float f0 = f_lg2(w0);
    float f1 = f_lg2(w1);
    float f2 = f_lg2(w2);

    // ---- branch-free Newton divided differences, ONE rcp ----
    float dlt = 2e-4f * q;
    float e01 = fmaxf(w0 - w1, dlt);
    float e12 = fmaxf(w1 - w2, dlt);
    float e02 = e01 + e12;
    float rall = f_rcp(e01 * (e12 * e02));
    float df01 = f0 - f1;
    float df12 = f1 - f2;
    float d01 = df01 * (e12 * e02) * rall;
    float gam = fmaf(df01, e12, -df12 * e01) * rall;
    float bet = d01 - gam * (w0 + w1);
    float alp = f0 - d01 * w0 + gam * (w0 * w1);

    // ---- A^2 (symmetric, 6 unique entries) ----
    float s00 = a00 * a00 + a10 * a10 + a20 * a20;
    float s11 = a10 * a10 + a11 * a11 + a21 * a21;
    float s22 = a20 * a20 + a21 * a21 + a22 * a22;
    float s10 = a10 * (a00 + a11) + a20 * a21;
    float s20 = a20 * (a00 + a22) + a10 * a21;
    float s21 = a21 * (a11 + a22) + a10 * a20;

    L.m00 = alp + bet * a00 + gam * s00;
    L.m11 = alp + bet * a11 + gam * s11;
    L.m22 = alp + bet * a22 + gam * s22;
    L.m10 = bet * a10 + gam * s10;
    L.m20 = bet * a20 + gam * s20;
    L.m21 = bet * a21 + gam * s21;
}

// One MATRIX per thread: even lanes process D1[i], odd lanes D2[i] (same i).
// The pair difference is formed with shfl_xor(1). Both lanes of a pair get
// identical t^2, so the total sum counts every pair twice — the global scale
// absorbs the 0.5. This halves per-thread work (one MUFU chain, not two
// back-to-back) and doubles warp-level parallelism at LOWER register cost:
// the ILP that R6-R10 failed to buy through the register file.
__global__ void __launch_bounds__(256)
loss_kernel(const float* __restrict__ d1, const float* __restrict__ d2,
            int nmat, float* __restrict__ out, double inv_n, unsigned int nblocks) {
    int tid = blockIdx.x * blockDim.x + threadIdx.x;
    int mat = tid >> 1;
    int sel = tid & 1;

    // clamp + weight so ALL lanes execute the shfls (pairs go invalid together)
    float wgt = (mat < nmat) ? 1.0f : 0.0f;
    int m = min(mat, nmat - 1);
    const float* g = (sel ? d2 : d1) + (size_t)m * 9;

    Sym3 L;
    log_spd3(g, L);

    float t, sd = 0.0f, soff = 0.0f;
    t = L.m00 - __shfl_xor_sync(0xffffffffu, L.m00, 1); sd   = fmaf(t, t, sd);
    t = L.m11 - __shfl_xor_sync(0xffffffffu, L.m11, 1); sd   = fmaf(t, t, sd);
    t = L.m22 - __shfl_xor_sync(0xffffffffu, L.m22, 1); sd   = fmaf(t, t, sd);
    t = L.m10 - __shfl_xor_sync(0xffffffffu, L.m10, 1); soff = fmaf(t, t, soff);
    t = L.m20 - __shfl_xor_sync(0xffffffffu, L.m20, 1); soff = fmaf(t, t, soff);
    t = L.m21 - __shfl_xor_sync(0xffffffffu, L.m21, 1); soff = fmaf(t, t, soff);
    float s = wgt * fmaf(2.0f, soff, sd);   // off-diagonals count twice

    // ---- block reduction ----
    #pragma unroll
    for (int off = 16; off > 0; off >>= 1)
        s += __shfl_xor_sync(0xffffffffu, s, off);

    __shared__ float sh[8];
    int lane = threadIdx.x & 31;
    int warp = threadIdx.x >> 5;
    if (lane == 0) sh[warp] = s;
    __syncthreads();
    if (warp == 0) {
        float v = (lane < 8) ? sh[lane] : 0.0f;
        #pragma unroll
        for (int off = 4; off > 0; off >>= 1)
            v += __shfl_xor_sync(0xffu, v, off);
        if (lane == 0) {
            atomicAdd(&g_accum, (double)v);
            __threadfence();
            // ticket wraps to 0 at nblocks-1: self-resets for the next replay
            unsigned int ticket = atomicInc(&g_count, nblocks - 1u);
            if (ticket == nblocks - 1u) {
                out[0] = (float)(g_accum * inv_n);
                g_accum = 0.0;    // restore invariant for next call/replay
            }
        }
    }
}

extern "C" void kernel_launch(void* const* d_in, const int* in_sizes, int n_in,
                              void* d_out, int out_size) {
    const float* d1 = (const float*)d_in[0];
    const float* d2 = (const float*)d_in[1];
    int n_elems = in_sizes[0];          // nmat * 9
    int nmat = n_elems / 9;

    int threads = 256;
    long long nthreads = 2LL * nmat;    // one matrix per thread
    unsigned int blocks = (unsigned int)((nthreads + threads - 1) / threads);
    // 0.5 (each pair counted by both lanes) * ln(2)^2 (base-2 logs) / n
    double inv_n = 0.5 * LN2SQ / (double)n_elems;
    loss_kernel<<<blocks, threads>>>(d1, d2, nmat, (float*)d_out, inv_n, blocks);
}

// round 14
// speedup vs baseline: 1.1686x; 1.1686x over previous
#include <cuda_runtime.h>
#include <math.h>
#include <stdint.h>

// ln(2)^2 — final scale converting lg2-unit squared-loss into natural-log units
#define LN2SQ 0.4804530139182014

// statically-zeroed accumulators; kernel self-resets them after each use,
// so the zero-invariant holds across the correctness run and every graph replay.
__device__ double g_accum = 0.0;
__device__ unsigned int g_count = 0u;

// ---- flag-independent fast approx intrinsics (MUFU paths) ----
__device__ __forceinline__ float f_rcp(float x)   { float y; asm("rcp.approx.f32 %0, %1;"   : "=f"(y) : "f"(x)); return y; }
__device__ __forceinline__ float f_rsqrt(float x) { float y; asm("rsqrt.approx.f32 %0, %1;" : "=f"(y) : "f"(x)); return y; }
__device__ __forceinline__ float f_sqrt(float x)  { float y; asm("sqrt.approx.f32 %0, %1;"  : "=f"(y) : "f"(x)); return y; }
__device__ __forceinline__ float f_lg2(float x)   { float y; asm("lg2.approx.f32 %0, %1;"   : "=f"(y) : "f"(x)); return y; }
__device__ __forceinline__ float f_cos(float x)   { float y; asm("cos.approx.f32 %0, %1;"   : "=f"(y) : "f"(x)); return y; }

// Abramowitz & Stegun 4.4.46: |err| <= 2e-8 rad on [0,1], extended to [-1,1]
__device__ __forceinline__ float fast_acos(float r) {
    float a = fabsf(r);
    float p = -0.0012624911f;
    p = fmaf(p, a,  0.0066700901f);
    p = fmaf(p, a, -0.0170881256f);
    p = fmaf(p, a,  0.0308918810f);
    p = fmaf(p, a, -0.0501743046f);
    p = fmaf(p, a,  0.0889789874f);
    p = fmaf(p, a, -0.2145988016f);
    p = fmaf(p, a,  1.5707963050f);
    float t = f_sqrt(fmaxf(1.0f - a, 0.0f)) * p;
    return (r < 0.0f) ? (3.14159265359f - t) : t;
}

struct Sym3 { float m00, m10, m11, m20, m21, m22; };

// logm (in lg2 units) of a 3x3 SPD matrix — the proven R9/R11 path:
// trig eigenvalues, A&S acos poly, single-rcp clamped Newton divided diffs.
__device__ __forceinline__ void log_spd3(const float* __restrict__ g, Sym3& L) {
    float a00 = g[0];
    float a10 = g[3];
    float a11 = g[4];
    float a20 = g[6];
    float a21 = g[7];
    float a22 = g[8];

    // ---- eigenvalues: trigonometric method (Smith) ----
    float q   = (a00 + a11 + a22) * (1.0f / 3.0f);
    float b00 = a00 - q, b11 = a11 - q, b22 = a22 - q;
    float p1  = a10 * a10 + a20 * a20 + a21 * a21;
    float p2  = b00 * b00 + b11 * b11 + b22 * b22 + 2.0f * p1;
    float x   = p2 * (1.0f / 6.0f);
    float rs  = f_rsqrt(fmaxf(x, 1e-30f));   // 1/sqrt(x)
    float p   = x * rs;                      // sqrt(x)

    float detB = b00 * (b11 * b22 - a21 * a21)
               - a10 * (a10 * b22 - a21 * a20)
               + a20 * (a10 * a21 - b11 * a20);
    float r = detB * (rs * rs) * (0.5f * rs);
    r = fmaxf(-1.0f, fminf(1.0f, r));        // also squashes NaN -> 1

    float phi = fast_acos(r) * (1.0f / 3.0f);
    float tp  = 2.0f * p;
    float w0 = fmaf(tp, f_cos(phi), q);                          // largest
    float w2 = fmaf(tp, f_cos(phi + 2.0943951023931953f), q);    // smallest
    float w1 = fmaf(3.0f, q, -w0) - w2;                          // middle

    // logs in base-2; final loss rescaled once by ln(2)^2
    float f0 = f_lg2(w0);
    float f1 = f_lg2(w1);
    float f2 = f_lg2(w2);

    // ---- branch-free Newton divided differences, ONE rcp ----
    float dlt = 2e-4f * q;
    float e01 = fmaxf(w0 - w1, dlt);
    float e12 = fmaxf(w1 - w2, dlt);
    float e02 = e01 + e12;
    float rall = f_rcp(e01 * (e12 * e02));
    float df01 = f0 - f1;
    float df12 = f1 - f2;
    float d01 = df01 * (e12 * e02) * rall;
    float gam = fmaf(df01, e12, -df12 * e01) * rall;
    float bet = d01 - gam * (w0 + w1);
    float alp = f0 - d01 * w0 + gam * (w0 * w1);

    // ---- A^2 (symmetric, 6 unique entries) ----
    float s00 = a00 * a00 + a10 * a10 + a20 * a20;
    float s11 = a10 * a10 + a11 * a11 + a21 * a21;
    float s22 = a20 * a20 + a21 * a21 + a22 * a22;
    float s10 = a10 * (a00 + a11) + a20 * a21;
    float s20 = a20 * (a00 + a22) + a10 * a21;
    float s21 = a21 * (a11 + a22) + a10 * a20;

    L.m00 = alp + bet * a00 + gam * s00;
    L.m11 = alp + bet * a11 + gam * s11;
    L.m22 = alp + bet * a22 + gam * s22;
    L.m10 = bet * a10 + gam * s10;
    L.m20 = bet * a20 + gam * s20;
    L.m21 = bet * a21 + gam * s21;
}

__global__ void __launch_bounds__(512)
loss_kernel(const float* __restrict__ d1, const float* __restrict__ d2,
            int nmat, float* __restrict__ out, double inv_n, unsigned int nblocks) {
    int i = blockIdx.x * blockDim.x + threadIdx.x;
    float s = 0.0f;
    if (i < nmat) {
        size_t off = (size_t)i * 9;
        Sym3 L1, L2;
        log_spd3(d1 + off, L1);
        log_spd3(d2 + off, L2);
        float t, soff = 0.0f;
        t = L1.m00 - L2.m00; s    = fmaf(t, t, s);
        t = L1.m11 - L2.m11; s    = fmaf(t, t, s);
        t = L1.m22 - L2.m22; s    = fmaf(t, t, s);
        t = L1.m10 - L2.m10; soff = fmaf(t, t, soff);
        t = L1.m20 - L2.m20; soff = fmaf(t, t, soff);
        t = L1.m21 - L2.m21; soff = fmaf(t, t, soff);
        s = fmaf(2.0f, soff, s);   // symmetric off-diagonals count twice
    }

    // ---- block reduction: shfl within warp, shfl-tree across 16 warps ----
    #pragma unroll
    for (int off = 16; off > 0; off >>= 1)
        s += __shfl_xor_sync(0xffffffffu, s, off);

    __shared__ float sh[16];
    int lane = threadIdx.x & 31;
    int warp = threadIdx.x >> 5;
    if (lane == 0) sh[warp] = s;
    __syncthreads();
    if (warp == 0) {
        float v = (lane < 16) ? sh[lane] : 0.0f;
        #pragma unroll
        for (int off = 8; off > 0; off >>= 1)
            v += __shfl_xor_sync(0xffffu, v, off);
        if (lane == 0) {
            atomicAdd(&g_accum, (double)v);
            __threadfence();
            // ticket wraps to 0 at nblocks-1: self-resets for the next replay
            unsigned int ticket = atomicInc(&g_count, nblocks - 1u);
            if (ticket == nblocks - 1u) {
                out[0] = (float)(g_accum * inv_n);
                g_accum = 0.0;    // restore invariant for next call/replay
            }
        }
    }
}

extern "C" void kernel_launch(void* const* d_in, const int* in_sizes, int n_in,
                              void* d_out, int out_size) {
    const float* d1 = (const float*)d_in[0];
    const float* d2 = (const float*)d_in[1];
    int n_elems = in_sizes[0];          // nmat * 9
    int nmat = n_elems / 9;

    int threads = 512;
    unsigned int blocks = (unsigned int)((nmat + threads - 1) / threads);
    // inv_n includes the ln(2)^2 rescale (logs computed in base 2)
    double inv_n = LN2SQ / (double)n_elems;
    loss_kernel<<<blocks, threads>>>(d1, d2, nmat, (float*)d_out, inv_n, blocks);
}

// round 15
// speedup vs baseline: 1.1982x; 1.0254x over previous
#include <cuda_runtime.h>
#include <math.h>
#include <stdint.h>

// ln(2)^2 — final scale converting lg2-unit squared-loss into natural-log units
#define LN2SQ 0.4804530139182014

// statically-zeroed accumulators; kernel self-resets them after each use,
// so the zero-invariant holds across the correctness run and every graph replay.
__device__ double g_accum = 0.0;
__device__ unsigned int g_count = 0u;

// ---- flag-independent fast approx intrinsics (MUFU paths) ----
__device__ __forceinline__ float f_rcp(float x)   { float y; asm("rcp.approx.f32 %0, %1;"   : "=f"(y) : "f"(x)); return y; }
__device__ __forceinline__ float f_rsqrt(float x) { float y; asm("rsqrt.approx.f32 %0, %1;" : "=f"(y) : "f"(x)); return y; }
__device__ __forceinline__ float f_sqrt(float x)  { float y; asm("sqrt.approx.f32 %0, %1;"  : "=f"(y) : "f"(x)); return y; }
__device__ __forceinline__ float f_lg2(float x)   { float y; asm("lg2.approx.f32 %0, %1;"   : "=f"(y) : "f"(x)); return y; }
__device__ __forceinline__ float f_cos(float x)   { float y; asm("cos.approx.f32 %0, %1;"   : "=f"(y) : "f"(x)); return y; }

// acos(r)/3 directly: A&S 4.4.46 with all coefficients pre-divided by 3,
// reflection constant = pi/3. |err| <= 7e-9 rad. Saves a multiply on the
// serial path between the acos select and the dependent cos MUFUs.
__device__ __forceinline__ float fast_acos_third(float r) {
    float a = fabsf(r);
    float p = -0.00042083036f;        // -0.0012624911 / 3
    p = fmaf(p, a,  0.00222336337f);  //  0.0066700901 / 3
    p = fmaf(p, a, -0.00569604187f);  // -0.0170881256 / 3
    p = fmaf(p, a,  0.01029729367f);  //  0.0308918810 / 3
    p = fmaf(p, a, -0.01672476820f);  // -0.0501743046 / 3
    p = fmaf(p, a,  0.02965966247f);  //  0.0889789874 / 3
    p = fmaf(p, a, -0.07153293387f);  // -0.2145988016 / 3
    p = fmaf(p, a,  0.52359876833f);  //  1.5707963050 / 3
    float t = f_sqrt(fmaxf(1.0f - a, 0.0f)) * p;
    return (r < 0.0f) ? (1.0471975512f - t) : t;   // pi/3 - t
}

struct Sym3 { float m00, m10, m11, m20, m21, m22; };

// logm (in lg2 units) of a 3x3 SPD matrix — the proven R9/R11 path:
// trig eigenvalues, A&S acos poly (1/3-folded), single-rcp clamped Newton
// divided differences.
__device__ __forceinline__ void log_spd3(const float* __restrict__ g, Sym3& L) {
    float a00 = g[0];
    float a10 = g[3];
    float a11 = g[4];
    float a20 = g[6];
    float a21 = g[7];
    float a22 = g[8];

    // ---- eigenvalues: trigonometric method (Smith) ----
    float q   = (a00 + a11 + a22) * (1.0f / 3.0f);
    float b00 = a00 - q, b11 = a11 - q, b22 = a22 - q;
    float p1  = a10 * a10 + a20 * a20 + a21 * a21;
    float p2  = b00 * b00 + b11 * b11 + b22 * b22 + 2.0f * p1;
    float x   = p2 * (1.0f / 6.0f);
    float rs  = f_rsqrt(fmaxf(x, 1e-30f));   // 1/sqrt(x)
    float p   = x * rs;                      // sqrt(x)

    float detB = b00 * (b11 * b22 - a21 * a21)
               - a10 * (a10 * b22 - a21 * a20)
               + a20 * (a10 * a21 - b11 * a20);
    float r = detB * (rs * rs) * (0.5f * rs);
    r = fmaxf(-1.0f, fminf(1.0f, r));        // also squashes NaN -> 1

    float phi = fast_acos_third(r);          // acos(r)/3
    float tp  = 2.0f * p;
    float w0 = fmaf(tp, f_cos(phi), q);                          // largest
    float w2 = fmaf(tp, f_cos(phi + 2.0943951023931953f), q);    // smallest
    float w1 = fmaf(3.0f, q, -w0) - w2;                          // middle

    // logs in base-2; final loss rescaled once by ln(2)^2
    float f0 = f_lg2(w0);
    float f1 = f_lg2(w1);
    float f2 = f_lg2(w2);

    // ---- branch-free Newton divided differences, ONE rcp ----
    float dlt = 2e-4f * q;
    float e01 = fmaxf(w0 - w1, dlt);
    float e12 = fmaxf(w1 - w2, dlt);
    float e02 = e01 + e12;
    float rall = f_rcp(e01 * (e12 * e02));
    float df01 = f0 - f1;
    float df12 = f1 - f2;
    float d01 = df01 * (e12 * e02) * rall;
    float gam = fmaf(df01, e12, -df12 * e01) * rall;
    float bet = d01 - gam * (w0 + w1);
    float alp = f0 - d01 * w0 + gam * (w0 * w1);

    // ---- A^2 (symmetric, 6 unique entries) ----
    float s00 = a00 * a00 + a10 * a10 + a20 * a20;
    float s11 = a10 * a10 + a11 * a11 + a21 * a21;
    float s22 = a20 * a20 + a21 * a21 + a22 * a22;
    float s10 = a10 * (a00 + a11) + a20 * a21;
    float s20 = a20 * (a00 + a22) + a10 * a21;
    float s21 = a21 * (a11 + a22) + a10 * a20;

    L.m00 = alp + bet * a00 + gam * s00;
    L.m11 = alp + bet * a11 + gam * s11;
    L.m22 = alp + bet * a22 + gam * s22;
    L.m10 = bet * a10 + gam * s10;
    L.m20 = bet * a20 + gam * s20;
    L.m21 = bet * a21 + gam * s21;
}

__global__ void __launch_bounds__(256)
loss_kernel(const float* __restrict__ d1, const float* __restrict__ d2,
            int nmat, float* __restrict__ out, double inv_n, unsigned int nblocks) {
    int i = blockIdx.x * blockDim.x + threadIdx.x;
    float s = 0.0f;
    if (i < nmat) {
        size_t off = (size_t)i * 9;
        Sym3 L1, L2;
        log_spd3(d1 + off, L1);
        log_spd3(d2 + off, L2);
        float t, soff = 0.0f;
        t = L1.m00 - L2.m00; s    = fmaf(t, t, s);
        t = L1.m11 - L2.m11; s    = fmaf(t, t, s);
        t = L1.m22 - L2.m22; s    = fmaf(t, t, s);
        t = L1.m10 - L2.m10; soff = fmaf(t, t, soff);
        t = L1.m20 - L2.m20; soff = fmaf(t, t, soff);
        t = L1.m21 - L2.m21; soff = fmaf(t, t, soff);
        s = fmaf(2.0f, soff, s);   // symmetric off-diagonals count twice
    }

    // ---- block reduction ----
    #pragma unroll
    for (int off = 16; off > 0; off >>= 1)
        s += __shfl_xor_sync(0xffffffffu, s, off);

    __shared__ float sh[8];
    int lane = threadIdx.x & 31;
    int warp = threadIdx.x >> 5;
    if (lane == 0) sh[warp] = s;
    __syncthreads();
    if (warp == 0) {
        float v = (lane < 8) ? sh[lane] : 0.0f;
        #pragma unroll
        for (int off = 4; off > 0; off >>= 1)
            v += __shfl_xor_sync(0xffu, v, off);
        if (lane == 0) {
            atomicAdd(&g_accum, (double)v);
            __threadfence();
            // ticket wraps to 0 at nblocks-1: self-resets for the next replay
            unsigned int ticket = atomicInc(&g_count, nblocks - 1u);
            if (ticket == nblocks - 1u) {
                out[0] = (float)(g_accum * inv_n);
                g_accum = 0.0;    // restore invariant for next call/replay
            }
        }
    }
}

extern "C" void kernel_launch(void* const* d_in, const int* in_sizes, int n_in,
                              void* d_out, int out_size) {
    const float* d1 = (const float*)d_in[0];
    const float* d2 = (const float*)d_in[1];
    int n_elems = in_sizes[0];          // nmat * 9
    int nmat = n_elems / 9;

    int threads = 256;
    unsigned int blocks = (unsigned int)((nmat + threads - 1) / threads);
    // inv_n includes the ln(2)^2 rescale (logs computed in base 2)
    double inv_n = LN2SQ / (double)n_elems;
    loss_kernel<<<blocks, threads>>>(d1, d2, nmat, (float*)d_out, inv_n, blocks);
}